// round 3
// baseline (speedup 1.0000x reference)
#include <cuda_runtime.h>
#include <cuda_bf16.h>
#include <math.h>

// ---------------- problem constants ----------------
#define NN 50000          // nodes
#define NE 800000         // edges
#define NF 32             // node feature
#define EF 8              // edge feature
#define ZD 72             // 2*NF + EF
#define HEADS 3
#define NG 64             // graphs
#define G1C 32            // GAT1 out channels per head
#define G2C 16            // GAT2 out channels per head
#define G1O (HEADS*G1C)   // 96
#define G2O (HEADS*G2C)   // 48
#define ETOT (NE + NN)    // edges + self loops

// ---------------- device scratch (static; no allocation allowed) ----------------
__device__ float d_agg [NN*NF];        // CGConv aggregation
__device__ float d_h1  [NN*NF];
__device__ float d_h2  [NN*NF];
__device__ float d_bufA[NN*G1O];       // hg (per-layer node transform)
__device__ float d_bufB[NN*G1O];       // GAT aggregation
__device__ float d_bufC[NN*G1O];       // layer outputs
__device__ float d_alsrc[NN*HEADS];
__device__ float d_aldst[NN*HEADS];
__device__ unsigned d_mmax[NN*HEADS];  // segment max (monotonic-uint encoded)
__device__ float d_ssum[NN*HEADS];
__device__ float d_p   [(ETOT)*HEADS + 16];
__device__ float d_pool[NG*G2O];
__device__ float d_cnt [NG];

// monotonic float<->uint for atomicMax over floats
__device__ __forceinline__ unsigned fenc(float f) {
    unsigned u = __float_as_uint(f);
    return (u & 0x80000000u) ? ~u : (u | 0x80000000u);
}
__device__ __forceinline__ float fdec(unsigned u) {
    return __uint_as_float((u & 0x80000000u) ? (u & 0x7fffffffu) : ~u);
}

// ---------------- utility fills ----------------
__global__ void fill_f(float* p, float v, int n) {
    int i = blockIdx.x * blockDim.x + threadIdx.x;
    if (i < n) p[i] = v;
}
__global__ void fill_u(unsigned* p, unsigned v, int n) {
    int i = blockIdx.x * blockDim.x + threadIdx.x;
    if (i < n) p[i] = v;
}

// ---------------- CGConv edge kernel ----------------
// z = [x[dst], x[src], e]; msg = sigmoid(z@Wf+bf) * softplus(z@Ws+bs); atomicAdd into agg[dst]
// TILE_E = 96 keeps static shared below the 48 KB ptxas limit:
//   zsh 96*73*4 = 28032 B, wf+ws = 2*72*32*4 = 18432 B, total 46464 B.
#define TILE_E 96
__global__ __launch_bounds__(TILE_E) void cg_edge(
    const float* __restrict__ xin, const float* __restrict__ eattr,
    const int* __restrict__ src, const int* __restrict__ dst,
    const float* __restrict__ Wf, const float* __restrict__ bf,
    const float* __restrict__ Ws, const float* __restrict__ bs,
    float* __restrict__ agg, int E)
{
    __shared__ float zsh[TILE_E * 73];      // padded rows -> conflict-free
    __shared__ float wf[ZD * NF];
    __shared__ float ws[ZD * NF];

    int tid = threadIdx.x;
    int e0 = blockIdx.x * TILE_E;
    for (int i = tid; i < ZD * NF; i += TILE_E) { wf[i] = Wf[i]; ws[i] = Ws[i]; }

    int warp = tid >> 5, lane = tid & 31;
    // gather z rows: one warp per edge iteration (coalesced 128B row reads)
    for (int e = warp; e < TILE_E; e += (TILE_E / 32)) {
        int ge = e0 + e;
        if (ge < E) {
            int d = dst[ge], s = src[ge];
            zsh[e * 73 + lane]      = xin[d * NF + lane];
            zsh[e * 73 + 32 + lane] = xin[s * NF + lane];
            if (lane < EF) zsh[e * 73 + 64 + lane] = eattr[ge * EF + lane];
        }
    }
    __syncthreads();

    int ge = e0 + tid;
    float accf[NF], accs[NF];
    if (ge < E) {
        #pragma unroll
        for (int c = 0; c < NF; c++) { accf[c] = bf[c]; accs[c] = bs[c]; }
        const float* zr = &zsh[tid * 73];
        #pragma unroll 4
        for (int k = 0; k < ZD; k++) {
            float zk = zr[k];
            const float* wfr = &wf[k * NF];
            const float* wsr = &ws[k * NF];
            #pragma unroll
            for (int c = 0; c < NF; c++) {
                accf[c] = fmaf(zk, wfr[c], accf[c]);
                accs[c] = fmaf(zk, wsr[c], accs[c]);
            }
        }
        // gate
        #pragma unroll
        for (int c = 0; c < NF; c++) {
            float f = accf[c], s2 = accs[c];
            float sig = 1.f / (1.f + __expf(-f));
            float sp  = fmaxf(s2, 0.f) + __logf(1.f + __expf(-fabsf(s2)));
            accf[c] = sig * sp;
        }
    }
    __syncthreads();   // all z reads done before reuse
    // stage messages in shared (stride 33: conflict-free column writes)
    float* msh = zsh;
    if (ge < E) {
        #pragma unroll
        for (int c = 0; c < NF; c++) msh[tid * 33 + c] = accf[c];
    }
    __syncthreads();
    // coalesced scatter: warp per edge, lane per channel
    for (int e = warp; e < TILE_E; e += (TILE_E / 32)) {
        int g2 = e0 + e;
        if (g2 < E) {
            int d = dst[g2];
            atomicAdd(&agg[d * NF + lane], msh[e * 33 + lane]);
        }
    }
}

// out = relu(agg + residual)
__global__ void cg_final(const float* __restrict__ agg, const float* __restrict__ res,
                         float* __restrict__ out, int n)
{
    int i = blockIdx.x * blockDim.x + threadIdx.x;
    if (i < n) out[i] = fmaxf(agg[i] + res[i], 0.f);
}

// ---------------- GAT kernels ----------------
// node transform: hg[n,:] = x[n,:] @ W
template<int IN, int OUT>
__global__ __launch_bounds__(128) void gat_gemm(
    const float* __restrict__ xin, const float* __restrict__ W,
    float* __restrict__ hg, int N)
{
    __shared__ float wsh[IN * OUT];
    __shared__ float xr[4][IN];
    for (int i = threadIdx.x; i < IN * OUT; i += 128) wsh[i] = W[i];
    __syncthreads();
    int warp = threadIdx.x >> 5, lane = threadIdx.x & 31;
    int n = blockIdx.x * 4 + warp;
    if (n >= N) return;
    for (int k = lane; k < IN; k += 32) xr[warp][k] = xin[n * IN + k];
    __syncwarp();
    #pragma unroll
    for (int j = 0; j < (OUT + 31) / 32; j++) {
        int c = lane + 32 * j;
        if (c < OUT) {
            float a = 0.f;
            #pragma unroll 4
            for (int k = 0; k < IN; k++) a = fmaf(xr[warp][k], wsh[k * OUT + c], a);
            hg[n * OUT + c] = a;
        }
    }
}

// attention logits per node/head
template<int C>
__global__ void gat_al(const float* __restrict__ hg,
                       const float* __restrict__ asrc, const float* __restrict__ adst,
                       float* __restrict__ alsrc, float* __restrict__ aldst, int N)
{
    int i = blockIdx.x * blockDim.x + threadIdx.x;
    if (i >= N * HEADS) return;
    int n = i / HEADS, h = i % HEADS;
    float s = 0.f, d = 0.f;
    #pragma unroll 4
    for (int c = 0; c < C; c++) {
        float v = hg[n * HEADS * C + h * C + c];
        s = fmaf(v, asrc[h * C + c], s);
        d = fmaf(v, adst[h * C + c], d);
    }
    alsrc[i] = s; aldst[i] = d;
}

__global__ void gat_edge_max(const float* __restrict__ alsrc, const float* __restrict__ aldst,
                             const int* __restrict__ src, const int* __restrict__ dst,
                             unsigned* __restrict__ m, int E, int N)
{
    int i = blockIdx.x * blockDim.x + threadIdx.x;
    if (i >= E + N) return;
    int s_, d_;
    if (i < E) { s_ = src[i]; d_ = dst[i]; } else { s_ = d_ = i - E; }
    #pragma unroll
    for (int h = 0; h < HEADS; h++) {
        float e = alsrc[s_ * HEADS + h] + aldst[d_ * HEADS + h];
        e = (e > 0.f) ? e : 0.2f * e;
        atomicMax(&m[d_ * HEADS + h], fenc(e));
    }
}

__global__ void gat_edge_p(const float* __restrict__ alsrc, const float* __restrict__ aldst,
                           const int* __restrict__ src, const int* __restrict__ dst,
                           const unsigned* __restrict__ m, float* __restrict__ p,
                           float* __restrict__ ssum, int E, int N)
{
    int i = blockIdx.x * blockDim.x + threadIdx.x;
    if (i >= E + N) return;
    int s_, d_;
    if (i < E) { s_ = src[i]; d_ = dst[i]; } else { s_ = d_ = i - E; }
    #pragma unroll
    for (int h = 0; h < HEADS; h++) {
        float e = alsrc[s_ * HEADS + h] + aldst[d_ * HEADS + h];
        e = (e > 0.f) ? e : 0.2f * e;
        float pv = __expf(e - fdec(m[d_ * HEADS + h]));
        p[i * HEADS + h] = pv;
        atomicAdd(&ssum[d_ * HEADS + h], pv);
    }
}

template<int OUT, int C>
__global__ void gat_agg(const float* __restrict__ hg, const float* __restrict__ p,
                        const float* __restrict__ ssum,
                        const int* __restrict__ src, const int* __restrict__ dst,
                        float* __restrict__ out, int E, int N)
{
    int widx = (blockIdx.x * blockDim.x + threadIdx.x) >> 5;
    int lane = threadIdx.x & 31;
    if (widx >= E + N) return;
    int s_, d_;
    if (widx < E) { s_ = src[widx]; d_ = dst[widx]; } else { s_ = d_ = widx - E; }
    float alpha[HEADS];
    #pragma unroll
    for (int h = 0; h < HEADS; h++)
        alpha[h] = p[widx * HEADS + h] / (ssum[d_ * HEADS + h] + 1e-16f);
    #pragma unroll
    for (int j = 0; j < (OUT + 31) / 32; j++) {
        int c = lane + 32 * j;
        if (c < OUT) {
            int h = c / C;
            atomicAdd(&out[d_ * OUT + c], hg[s_ * OUT + c] * alpha[h]);
        }
    }
}

// out = relu(agg + bias[c])
template<int OUT>
__global__ void gat_final(const float* __restrict__ agg, const float* __restrict__ bias,
                          float* __restrict__ out, int N)
{
    int i = blockIdx.x * blockDim.x + threadIdx.x;
    if (i >= N * OUT) return;
    out[i] = fmaxf(agg[i] + bias[i % OUT], 0.f);
}

// ---------------- pooling + head ----------------
__global__ void pool_kernel(const float* __restrict__ g2, const int* __restrict__ batch,
                            float* __restrict__ pooled, float* __restrict__ cnt, int N)
{
    int i = blockIdx.x * blockDim.x + threadIdx.x;
    if (i >= N * G2O) return;
    int n = i / G2O, c = i % G2O;
    int b = batch[n];
    atomicAdd(&pooled[b * G2O + c], g2[i]);
    if (c == 0) atomicAdd(&cnt[b], 1.f);
}

__global__ void head_kernel(const float* __restrict__ pooled, const float* __restrict__ cnt,
                            const float* __restrict__ Wl1, const float* __restrict__ bl1,
                            const float* __restrict__ Wl2, const float* __restrict__ bl2,
                            float* __restrict__ out)
{
    __shared__ float mean[G2O];
    __shared__ float l1[16];
    int g = blockIdx.x, t = threadIdx.x;
    float c = fmaxf(cnt[g], 1.f);
    if (t < G2O) mean[t] = pooled[g * G2O + t] / c;
    __syncthreads();
    if (t < 16) {
        float a = bl1[t];
        #pragma unroll 4
        for (int k = 0; k < G2O; k++) a = fmaf(mean[k], Wl1[k * 16 + t], a);
        l1[t] = fmaxf(a, 0.f);
    }
    __syncthreads();
    if (t < 10) {
        float a = bl2[t];
        #pragma unroll
        for (int k = 0; k < 16; k++) a = fmaf(l1[k], Wl2[k * 10 + t], a);
        out[g * 10 + t] = a;
    }
}

// ---------------- launch ----------------
static inline int cdiv(int a, int b) { return (a + b - 1) / b; }

extern "C" void kernel_launch(void* const* d_in, const int* in_sizes, int n_in,
                              void* d_out, int out_size)
{
    const float* x     = (const float*)d_in[0];
    const float* eattr = (const float*)d_in[1];
    const int*   eidx  = (const int*)  d_in[2];
    const int*   batch = (const int*)  d_in[3];
    const float* Wf1 = (const float*)d_in[4];  const float* bf1 = (const float*)d_in[5];
    const float* Ws1 = (const float*)d_in[6];  const float* bs1 = (const float*)d_in[7];
    const float* Wf2 = (const float*)d_in[8];  const float* bf2 = (const float*)d_in[9];
    const float* Ws2 = (const float*)d_in[10]; const float* bs2 = (const float*)d_in[11];
    const float* Wg1 = (const float*)d_in[12];
    const float* as1 = (const float*)d_in[13]; const float* ad1 = (const float*)d_in[14];
    const float* bg1 = (const float*)d_in[15];
    const float* Wg2 = (const float*)d_in[16];
    const float* as2 = (const float*)d_in[17]; const float* ad2 = (const float*)d_in[18];
    const float* bg2 = (const float*)d_in[19];
    const float* Wl1 = (const float*)d_in[20]; const float* bl1 = (const float*)d_in[21];
    const float* Wl2 = (const float*)d_in[22]; const float* bl2 = (const float*)d_in[23];
    float* out = (float*)d_out;

    const int N = in_sizes[0] / NF;          // 50000
    const int E = in_sizes[2] / 2;           // 800000
    const int Etot = E + N;
    const int* src = eidx;
    const int* dst = eidx + E;

    float *agg, *h1, *h2, *bufA, *bufB, *bufC, *alsrc, *aldst, *ssum, *p, *pool, *cnt;
    unsigned* mmax;
    cudaGetSymbolAddress((void**)&agg,  d_agg);
    cudaGetSymbolAddress((void**)&h1,   d_h1);
    cudaGetSymbolAddress((void**)&h2,   d_h2);
    cudaGetSymbolAddress((void**)&bufA, d_bufA);
    cudaGetSymbolAddress((void**)&bufB, d_bufB);
    cudaGetSymbolAddress((void**)&bufC, d_bufC);
    cudaGetSymbolAddress((void**)&alsrc,d_alsrc);
    cudaGetSymbolAddress((void**)&aldst,d_aldst);
    cudaGetSymbolAddress((void**)&mmax, d_mmax);
    cudaGetSymbolAddress((void**)&ssum, d_ssum);
    cudaGetSymbolAddress((void**)&p,    d_p);
    cudaGetSymbolAddress((void**)&pool, d_pool);
    cudaGetSymbolAddress((void**)&cnt,  d_cnt);

    const unsigned NEG_INF_ENC = 0x007fffffu;  // fenc(-inf)

    // ---- CGConv 1 ----
    fill_f<<<cdiv(N*NF,256),256>>>(agg, 0.f, N*NF);
    cg_edge<<<cdiv(E,TILE_E),TILE_E>>>(x, eattr, src, dst, Wf1, bf1, Ws1, bs1, agg, E);
    cg_final<<<cdiv(N*NF,256),256>>>(agg, x, h1, N*NF);

    // ---- CGConv 2 ----
    fill_f<<<cdiv(N*NF,256),256>>>(agg, 0.f, N*NF);
    cg_edge<<<cdiv(E,TILE_E),TILE_E>>>(h1, eattr, src, dst, Wf2, bf2, Ws2, bs2, agg, E);
    cg_final<<<cdiv(N*NF,256),256>>>(agg, h1, h2, N*NF);

    // ---- GAT 1 (32 -> 3x32) ----
    gat_gemm<NF, G1O><<<cdiv(N,4),128>>>(h2, Wg1, bufA, N);
    gat_al<G1C><<<cdiv(N*HEADS,256),256>>>(bufA, as1, ad1, alsrc, aldst, N);
    fill_u<<<cdiv(N*HEADS,256),256>>>(mmax, NEG_INF_ENC, N*HEADS);
    fill_f<<<cdiv(N*HEADS,256),256>>>(ssum, 0.f, N*HEADS);
    fill_f<<<cdiv(N*G1O,256),256>>>(bufB, 0.f, N*G1O);
    gat_edge_max<<<cdiv(Etot,256),256>>>(alsrc, aldst, src, dst, mmax, E, N);
    gat_edge_p<<<cdiv(Etot,256),256>>>(alsrc, aldst, src, dst, mmax, p, ssum, E, N);
    gat_agg<G1O, G1C><<<cdiv(Etot*32,256),256>>>(bufA, p, ssum, src, dst, bufB, E, N);
    gat_final<G1O><<<cdiv(N*G1O,256),256>>>(bufB, bg1, bufC, N);

    // ---- GAT 2 (96 -> 3x16) ----
    gat_gemm<G1O, G2O><<<cdiv(N,4),128>>>(bufC, Wg2, bufA, N);
    gat_al<G2C><<<cdiv(N*HEADS,256),256>>>(bufA, as2, ad2, alsrc, aldst, N);
    fill_u<<<cdiv(N*HEADS,256),256>>>(mmax, NEG_INF_ENC, N*HEADS);
    fill_f<<<cdiv(N*HEADS,256),256>>>(ssum, 0.f, N*HEADS);
    fill_f<<<cdiv(N*G2O,256),256>>>(bufB, 0.f, N*G2O);
    gat_edge_max<<<cdiv(Etot,256),256>>>(alsrc, aldst, src, dst, mmax, E, N);
    gat_edge_p<<<cdiv(Etot,256),256>>>(alsrc, aldst, src, dst, mmax, p, ssum, E, N);
    gat_agg<G2O, G2C><<<cdiv(Etot*32,256),256>>>(bufA, p, ssum, src, dst, bufB, E, N);
    gat_final<G2O><<<cdiv(N*G2O,256),256>>>(bufB, bg2, bufC, N);

    // ---- pool + head ----
    fill_f<<<cdiv(NG*G2O,256),256>>>(pool, 0.f, NG*G2O);
    fill_f<<<1,64>>>(cnt, 0.f, NG);
    pool_kernel<<<cdiv(N*G2O,256),256>>>(bufC, batch, pool, cnt, N);
    head_kernel<<<NG,64>>>(pool, cnt, Wl1, bl1, Wl2, bl2, out);
}

// round 4
// speedup vs baseline: 1.7465x; 1.7465x over previous
#include <cuda_runtime.h>
#include <cuda_bf16.h>
#include <math.h>

// ---------------- problem constants ----------------
#define NN 50000
#define NE 800000
#define NF 32
#define EF 8
#define ZD 72
#define HEADS 3
#define NG 64
#define G1C 32
#define G2C 16
#define G1O (HEADS*G1C)   // 96
#define G2O (HEADS*G2C)   // 48
#define ETOT (NE + NN)

// ---------------- device scratch ----------------
__device__ float d_agg [NN*NF];
__device__ float d_h1  [NN*NF];
__device__ float d_h2  [NN*NF];
__device__ float d_prec[NN*128];       // CGConv node-precompute: [fD|fS|sD|sS] x32
__device__ float d_bufA[NN*G1O];       // hg
__device__ float d_bufB[NN*G1O];       // GAT unnormalized aggregation
__device__ float d_bufC[NN*G1O];       // layer outputs
__device__ float d_alsrc[NN*HEADS];
__device__ float d_aldst[NN*HEADS];
__device__ float d_ssum[NN*HEADS];
__device__ float d_pool[NG*G2O];
__device__ float d_cnt [NG];

// ---------------- utility fills ----------------
__global__ void fill_f(float* p, float v, int n) {
    int i = blockIdx.x * blockDim.x + threadIdx.x;
    if (i < n) p[i] = v;
}

// ---------------- CGConv: node precompute ----------------
// prec[n][c]: c<32: x[n]@Wf[0:32] + bf ; c<64: x[n]@Wf[32:64] ;
//             c<96: x[n]@Ws[0:32] + bs ; else: x[n]@Ws[32:64]
__global__ __launch_bounds__(256) void cg_node_pre(
    const float* __restrict__ x,
    const float* __restrict__ Wf, const float* __restrict__ bf,
    const float* __restrict__ Ws, const float* __restrict__ bs,
    float* __restrict__ prec, int N)
{
    __shared__ float wc[32 * 128];   // 16 KB combined weight
    for (int idx = threadIdx.x; idx < 32 * 128; idx += 256) {
        int k = idx >> 7, c = idx & 127;
        float v;
        if      (c < 32)  v = Wf[k * 32 + c];
        else if (c < 64)  v = Wf[(32 + k) * 32 + (c - 32)];
        else if (c < 96)  v = Ws[k * 32 + (c - 64)];
        else              v = Ws[(32 + k) * 32 + (c - 96)];
        wc[idx] = v;
    }
    __syncthreads();
    int warp = threadIdx.x >> 5, lane = threadIdx.x & 31;
    int n = blockIdx.x * 8 + warp;
    if (n >= N) return;
    float xv = x[n * 32 + lane];
    int cbase = lane * 4;
    float4 acc = make_float4(0.f, 0.f, 0.f, 0.f);
    #pragma unroll
    for (int k = 0; k < 32; k++) {
        float xk = __shfl_sync(0xffffffffu, xv, k);
        float4 w = *(const float4*)&wc[k * 128 + cbase];
        acc.x = fmaf(xk, w.x, acc.x);
        acc.y = fmaf(xk, w.y, acc.y);
        acc.z = fmaf(xk, w.z, acc.z);
        acc.w = fmaf(xk, w.w, acc.w);
    }
    if (cbase < 32) {            // fD part: add bf
        acc.x += bf[cbase]; acc.y += bf[cbase+1]; acc.z += bf[cbase+2]; acc.w += bf[cbase+3];
    } else if (cbase >= 64 && cbase < 96) {   // sD part: add bs
        int b0 = cbase - 64;
        acc.x += bs[b0]; acc.y += bs[b0+1]; acc.z += bs[b0+2]; acc.w += bs[b0+3];
    }
    *(float4*)&prec[n * 128 + cbase] = acc;
}

// ---------------- CGConv: edge pass (warp per edge, grid-stride) ----------------
__global__ __launch_bounds__(256) void cg_edge2(
    const float* __restrict__ prec, const float* __restrict__ eattr,
    const int* __restrict__ src, const int* __restrict__ dst,
    const float* __restrict__ Wf, const float* __restrict__ Ws,
    float* __restrict__ agg, int E)
{
    __shared__ float wfb[EF * 32], wsb[EF * 32];   // bottom 8 rows of Wf/Ws
    int t = threadIdx.x;
    if (t < EF * 32) {
        int k = t >> 5, c = t & 31;
        wfb[t] = Wf[(64 + k) * 32 + c];
        wsb[t] = Ws[(64 + k) * 32 + c];
    }
    __syncthreads();
    int lane = t & 31;
    int warpg = blockIdx.x * 8 + (t >> 5);
    int nw = gridDim.x * 8;
    for (int e = warpg; e < E; e += nw) {
        int s = __ldg(&src[e]), d = __ldg(&dst[e]);
        const float* pd = prec + d * 128;
        const float* ps = prec + s * 128;
        float f  = pd[lane]      + ps[32 + lane];
        float sv = pd[64 + lane] + ps[96 + lane];
        #pragma unroll
        for (int k = 0; k < EF; k++) {
            float ek = __ldg(&eattr[e * EF + k]);   // warp-uniform broadcast
            f  = fmaf(ek, wfb[k * 32 + lane], f);
            sv = fmaf(ek, wsb[k * 32 + lane], sv);
        }
        float sig = 1.f / (1.f + __expf(-f));
        float sp  = fmaxf(sv, 0.f) + __logf(1.f + __expf(-fabsf(sv)));
        atomicAdd(&agg[d * 32 + lane], sig * sp);
    }
}

// out = relu(agg + residual)
__global__ void cg_final(const float* __restrict__ agg, const float* __restrict__ res,
                         float* __restrict__ out, int n)
{
    int i = blockIdx.x * blockDim.x + threadIdx.x;
    if (i < n) out[i] = fmaxf(agg[i] + res[i], 0.f);
}

// ---------------- GAT kernels ----------------
template<int IN, int OUT>
__global__ __launch_bounds__(128) void gat_gemm(
    const float* __restrict__ xin, const float* __restrict__ W,
    float* __restrict__ hg, int N)
{
    __shared__ float wsh[IN * OUT];
    __shared__ float xr[4][IN];
    for (int i = threadIdx.x; i < IN * OUT; i += 128) wsh[i] = W[i];
    __syncthreads();
    int warp = threadIdx.x >> 5, lane = threadIdx.x & 31;
    int n = blockIdx.x * 4 + warp;
    if (n >= N) return;
    for (int k = lane; k < IN; k += 32) xr[warp][k] = xin[n * IN + k];
    __syncwarp();
    #pragma unroll
    for (int j = 0; j < (OUT + 31) / 32; j++) {
        int c = lane + 32 * j;
        if (c < OUT) {
            float a = 0.f;
            #pragma unroll 4
            for (int k = 0; k < IN; k++) a = fmaf(xr[warp][k], wsh[k * OUT + c], a);
            hg[n * OUT + c] = a;
        }
    }
}

template<int C>
__global__ void gat_al(const float* __restrict__ hg,
                       const float* __restrict__ asrc, const float* __restrict__ adst,
                       float* __restrict__ alsrc, float* __restrict__ aldst, int N)
{
    int i = blockIdx.x * blockDim.x + threadIdx.x;
    if (i >= N * HEADS) return;
    int n = i / HEADS, h = i % HEADS;
    float s = 0.f, d = 0.f;
    #pragma unroll 4
    for (int c = 0; c < C; c++) {
        float v = hg[n * HEADS * C + h * C + c];
        s = fmaf(v, asrc[h * C + c], s);
        d = fmaf(v, adst[h * C + c], d);
    }
    alsrc[i] = s; aldst[i] = d;
}

// Fused single edge pass: unnormalized exp-weighted scatter + per-head sum.
// (no max-subtraction: logits are O(1), exp cannot overflow fp32; softmax is
//  shift-invariant so result matches reference.)
template<int OUT, int C>
__global__ __launch_bounds__(256) void gat_edge_fused(
    const float* __restrict__ hg,
    const float* __restrict__ alsrc, const float* __restrict__ aldst,
    const int* __restrict__ src, const int* __restrict__ dst,
    float* __restrict__ outagg, float* __restrict__ ssum, int E, int N)
{
    int lane = threadIdx.x & 31;
    int warpg = blockIdx.x * 8 + (threadIdx.x >> 5);
    int nw = gridDim.x * 8;
    for (int i = warpg; i < E + N; i += nw) {
        int s_, d_;
        if (i < E) { s_ = __ldg(&src[i]); d_ = __ldg(&dst[i]); }
        else       { s_ = d_ = i - E; }
        #pragma unroll
        for (int j = 0; j < (OUT + 31) / 32; j++) {
            int c = lane + 32 * j;
            if (c < OUT) {
                int h = c / C;
                float e = alsrc[s_ * HEADS + h] + aldst[d_ * HEADS + h];
                e = (e > 0.f) ? e : 0.2f * e;
                float pv = __expf(e);
                atomicAdd(&outagg[d_ * OUT + c], hg[s_ * OUT + c] * pv);
            }
        }
        if (lane < HEADS) {
            float e = alsrc[s_ * HEADS + lane] + aldst[d_ * HEADS + lane];
            e = (e > 0.f) ? e : 0.2f * e;
            atomicAdd(&ssum[d_ * HEADS + lane], __expf(e));
        }
    }
}

// out = relu(agg / ssum + bias)
template<int OUT, int C>
__global__ void gat_final2(const float* __restrict__ agg, const float* __restrict__ ssum,
                           const float* __restrict__ bias, float* __restrict__ out, int N)
{
    int i = blockIdx.x * blockDim.x + threadIdx.x;
    if (i >= N * OUT) return;
    int n = i / OUT, c = i % OUT;
    int h = c / C;
    out[i] = fmaxf(agg[i] / (ssum[n * HEADS + h] + 1e-16f) + bias[c], 0.f);
}

// ---------------- pooling + head ----------------
__global__ void pool_kernel(const float* __restrict__ g2, const int* __restrict__ batch,
                            float* __restrict__ pooled, float* __restrict__ cnt, int N)
{
    int i = blockIdx.x * blockDim.x + threadIdx.x;
    if (i >= N * G2O) return;
    int n = i / G2O, c = i % G2O;
    int b = batch[n];
    atomicAdd(&pooled[b * G2O + c], g2[i]);
    if (c == 0) atomicAdd(&cnt[b], 1.f);
}

__global__ void head_kernel(const float* __restrict__ pooled, const float* __restrict__ cnt,
                            const float* __restrict__ Wl1, const float* __restrict__ bl1,
                            const float* __restrict__ Wl2, const float* __restrict__ bl2,
                            float* __restrict__ out)
{
    __shared__ float mean[G2O];
    __shared__ float l1[16];
    int g = blockIdx.x, t = threadIdx.x;
    float c = fmaxf(cnt[g], 1.f);
    if (t < G2O) mean[t] = pooled[g * G2O + t] / c;
    __syncthreads();
    if (t < 16) {
        float a = bl1[t];
        #pragma unroll 4
        for (int k = 0; k < G2O; k++) a = fmaf(mean[k], Wl1[k * 16 + t], a);
        l1[t] = fmaxf(a, 0.f);
    }
    __syncthreads();
    if (t < 10) {
        float a = bl2[t];
        #pragma unroll
        for (int k = 0; k < 16; k++) a = fmaf(l1[k], Wl2[k * 10 + t], a);
        out[g * 10 + t] = a;
    }
}

// ---------------- launch ----------------
static inline int cdiv(int a, int b) { return (a + b - 1) / b; }

extern "C" void kernel_launch(void* const* d_in, const int* in_sizes, int n_in,
                              void* d_out, int out_size)
{
    const float* x     = (const float*)d_in[0];
    const float* eattr = (const float*)d_in[1];
    const int*   eidx  = (const int*)  d_in[2];
    const int*   batch = (const int*)  d_in[3];
    const float* Wf1 = (const float*)d_in[4];  const float* bf1 = (const float*)d_in[5];
    const float* Ws1 = (const float*)d_in[6];  const float* bs1 = (const float*)d_in[7];
    const float* Wf2 = (const float*)d_in[8];  const float* bf2 = (const float*)d_in[9];
    const float* Ws2 = (const float*)d_in[10]; const float* bs2 = (const float*)d_in[11];
    const float* Wg1 = (const float*)d_in[12];
    const float* as1 = (const float*)d_in[13]; const float* ad1 = (const float*)d_in[14];
    const float* bg1 = (const float*)d_in[15];
    const float* Wg2 = (const float*)d_in[16];
    const float* as2 = (const float*)d_in[17]; const float* ad2 = (const float*)d_in[18];
    const float* bg2 = (const float*)d_in[19];
    const float* Wl1 = (const float*)d_in[20]; const float* bl1 = (const float*)d_in[21];
    const float* Wl2 = (const float*)d_in[22]; const float* bl2 = (const float*)d_in[23];
    float* out = (float*)d_out;

    const int N = in_sizes[0] / NF;
    const int E = in_sizes[2] / 2;
    const int* src = eidx;
    const int* dst = eidx + E;

    float *agg, *h1, *h2, *prec, *bufA, *bufB, *bufC, *alsrc, *aldst, *ssum, *pool, *cnt;
    cudaGetSymbolAddress((void**)&agg,  d_agg);
    cudaGetSymbolAddress((void**)&h1,   d_h1);
    cudaGetSymbolAddress((void**)&h2,   d_h2);
    cudaGetSymbolAddress((void**)&prec, d_prec);
    cudaGetSymbolAddress((void**)&bufA, d_bufA);
    cudaGetSymbolAddress((void**)&bufB, d_bufB);
    cudaGetSymbolAddress((void**)&bufC, d_bufC);
    cudaGetSymbolAddress((void**)&alsrc,d_alsrc);
    cudaGetSymbolAddress((void**)&aldst,d_aldst);
    cudaGetSymbolAddress((void**)&ssum, d_ssum);
    cudaGetSymbolAddress((void**)&pool, d_pool);
    cudaGetSymbolAddress((void**)&cnt,  d_cnt);

    const int EGRID = 1184;   // grid-stride edge kernels: 8 blocks/SM x 148 SMs

    // ---- CGConv 1 ----
    fill_f<<<cdiv(N*NF,256),256>>>(agg, 0.f, N*NF);
    cg_node_pre<<<cdiv(N,8),256>>>(x, Wf1, bf1, Ws1, bs1, prec, N);
    cg_edge2<<<EGRID,256>>>(prec, eattr, src, dst, Wf1, Ws1, agg, E);
    cg_final<<<cdiv(N*NF,256),256>>>(agg, x, h1, N*NF);

    // ---- CGConv 2 ----
    fill_f<<<cdiv(N*NF,256),256>>>(agg, 0.f, N*NF);
    cg_node_pre<<<cdiv(N,8),256>>>(h1, Wf2, bf2, Ws2, bs2, prec, N);
    cg_edge2<<<EGRID,256>>>(prec, eattr, src, dst, Wf2, Ws2, agg, E);
    cg_final<<<cdiv(N*NF,256),256>>>(agg, h1, h2, N*NF);

    // ---- GAT 1 (32 -> 3x32) ----
    gat_gemm<NF, G1O><<<cdiv(N,4),128>>>(h2, Wg1, bufA, N);
    gat_al<G1C><<<cdiv(N*HEADS,256),256>>>(bufA, as1, ad1, alsrc, aldst, N);
    fill_f<<<cdiv(N*HEADS,256),256>>>(ssum, 0.f, N*HEADS);
    fill_f<<<cdiv(N*G1O,256),256>>>(bufB, 0.f, N*G1O);
    gat_edge_fused<G1O, G1C><<<EGRID,256>>>(bufA, alsrc, aldst, src, dst, bufB, ssum, E, N);
    gat_final2<G1O, G1C><<<cdiv(N*G1O,256),256>>>(bufB, ssum, bg1, bufC, N);

    // ---- GAT 2 (96 -> 3x16) ----
    gat_gemm<G1O, G2O><<<cdiv(N,4),128>>>(bufC, Wg2, bufA, N);
    gat_al<G2C><<<cdiv(N*HEADS,256),256>>>(bufA, as2, ad2, alsrc, aldst, N);
    fill_f<<<cdiv(N*HEADS,256),256>>>(ssum, 0.f, N*HEADS);
    fill_f<<<cdiv(N*G2O,256),256>>>(bufB, 0.f, N*G2O);
    gat_edge_fused<G2O, G2C><<<EGRID,256>>>(bufA, alsrc, aldst, src, dst, bufB, ssum, E, N);
    gat_final2<G2O, G2C><<<cdiv(N*G2O,256),256>>>(bufB, ssum, bg2, bufC, N);

    // ---- pool + head ----
    fill_f<<<cdiv(NG*G2O,256),256>>>(pool, 0.f, NG*G2O);
    fill_f<<<1,64>>>(cnt, 0.f, NG);
    pool_kernel<<<cdiv(N*G2O,256),256>>>(bufC, batch, pool, cnt, N);
    head_kernel<<<NG,64>>>(pool, cnt, Wl1, bl1, Wl2, bl2, out);
}

// round 6
// speedup vs baseline: 2.0346x; 1.1650x over previous
#include <cuda_runtime.h>
#include <cuda_bf16.h>
#include <math.h>

// ---------------- problem constants ----------------
#define NN 50000
#define NE 800000
#define NF 32
#define EF 8
#define HEADS 3
#define NG 64
#define G1C 32
#define G2C 16
#define G1O (HEADS*G1C)   // 96
#define G2O (HEADS*G2C)   // 48

// ---------------- device scratch (16B-aligned: vector loads used) ----------------
__device__ __align__(16) float d_h1  [NN*NF];
__device__ __align__(16) float d_h2  [NN*NF];
__device__ __align__(16) float d_prec[NN*128];   // [fD|fS|sD|sS] x32
__device__ __align__(16) float d_bufA[NN*G1O];   // hg
__device__ __align__(16) float d_bufC[NN*G1O];   // layer outputs
__device__ __align__(16) float d_alsrc[NN*4];    // padded to 4 for float4 loads
__device__ __align__(16) float d_aldst[NN*4];
__device__ __align__(16) float d_pool[NG*G2O];
__device__ float d_cnt [NG];
// CSR
__device__ int  d_deg   [NN];
__device__ int  d_rowptr[NN + 1];
__device__ int  d_cursor[NN];
__device__ __align__(16) int2 d_adj[NE];         // (src, edge_id) sorted by dst

// ---------------- utility ----------------
__global__ void fill_f(float* p, float v, int n) {
    int i = blockIdx.x * blockDim.x + threadIdx.x;
    if (i < n) p[i] = v;
}
__global__ void fill_i(int* p, int v, int n) {
    int i = blockIdx.x * blockDim.x + threadIdx.x;
    if (i < n) p[i] = v;
}

// ---------------- CSR construction ----------------
__global__ void csr_hist(const int* __restrict__ dst, int* __restrict__ deg, int E) {
    int i = blockIdx.x * blockDim.x + threadIdx.x;
    if (i < E) atomicAdd(&deg[dst[i]], 1);
}

// single-block exclusive scan over deg -> rowptr (+cursor copy), rowptr[N]=E
__global__ __launch_bounds__(1024) void csr_scan(const int* __restrict__ deg,
                                                 int* __restrict__ rowptr,
                                                 int* __restrict__ cursor, int N)
{
    __shared__ int tsum[1024];
    int t = threadIdx.x;
    int per = (N + 1023) / 1024;
    int start = t * per, end = min(start + per, N);
    int s = 0;
    for (int i = start; i < end; i++) s += deg[i];
    tsum[t] = s;
    __syncthreads();
    int inc = s;
    for (int off = 1; off < 1024; off <<= 1) {
        int v = (t >= off) ? tsum[t - off] : 0;
        __syncthreads();
        tsum[t] += v;
        __syncthreads();
    }
    int run = tsum[t] - inc;   // exclusive prefix
    for (int i = start; i < end; i++) {
        rowptr[i] = run; cursor[i] = run;
        run += deg[i];
    }
    if (t == 1023) rowptr[N] = run;
}

__global__ void csr_scatter(const int* __restrict__ src, const int* __restrict__ dst,
                            int* __restrict__ cursor, int2* __restrict__ adj, int E)
{
    int i = blockIdx.x * blockDim.x + threadIdx.x;
    if (i < E) {
        int d = dst[i];
        int pos = atomicAdd(&cursor[d], 1);
        adj[pos] = make_int2(src[i], i);
    }
}

// ---------------- CGConv: node precompute ----------------
__global__ __launch_bounds__(256) void cg_node_pre(
    const float* __restrict__ x,
    const float* __restrict__ Wf, const float* __restrict__ bf,
    const float* __restrict__ Ws, const float* __restrict__ bs,
    float* __restrict__ prec, int N)
{
    __shared__ float wc[32 * 128];
    for (int idx = threadIdx.x; idx < 32 * 128; idx += 256) {
        int k = idx >> 7, c = idx & 127;
        float v;
        if      (c < 32)  v = Wf[k * 32 + c];
        else if (c < 64)  v = Wf[(32 + k) * 32 + (c - 32)];
        else if (c < 96)  v = Ws[k * 32 + (c - 64)];
        else              v = Ws[(32 + k) * 32 + (c - 96)];
        wc[idx] = v;
    }
    __syncthreads();
    int warp = threadIdx.x >> 5, lane = threadIdx.x & 31;
    int n = blockIdx.x * 8 + warp;
    if (n >= N) return;
    float xv = x[n * 32 + lane];
    int cbase = lane * 4;
    float4 acc = make_float4(0.f, 0.f, 0.f, 0.f);
    #pragma unroll
    for (int k = 0; k < 32; k++) {
        float xk = __shfl_sync(0xffffffffu, xv, k);
        float4 w = *(const float4*)&wc[k * 128 + cbase];
        acc.x = fmaf(xk, w.x, acc.x);
        acc.y = fmaf(xk, w.y, acc.y);
        acc.z = fmaf(xk, w.z, acc.z);
        acc.w = fmaf(xk, w.w, acc.w);
    }
    if (cbase < 32) {
        acc.x += bf[cbase]; acc.y += bf[cbase+1]; acc.z += bf[cbase+2]; acc.w += bf[cbase+3];
    } else if (cbase >= 64 && cbase < 96) {
        int b0 = cbase - 64;
        acc.x += bs[b0]; acc.y += bs[b0+1]; acc.z += bs[b0+2]; acc.w += bs[b0+3];
    }
    *(float4*)&prec[n * 128 + cbase] = acc;
}

// ---------------- CGConv: pull aggregation (warp per dst node) ----------------
// out[n] = relu( sum_{e->n} sigmoid(f)*softplus(s) + res[n] )
__global__ __launch_bounds__(256) void cg_pull(
    const float* __restrict__ prec, const float* __restrict__ eattr,
    const int2* __restrict__ adj, const int* __restrict__ rowptr,
    const float* __restrict__ Wf, const float* __restrict__ Ws,
    const float* __restrict__ res, float* __restrict__ out, int N)
{
    __shared__ float wfb[EF * 32], wsb[EF * 32];
    int t = threadIdx.x;
    if (t < EF * 32) {
        int k = t >> 5, c = t & 31;
        wfb[t] = Wf[(64 + k) * 32 + c];
        wsb[t] = Ws[(64 + k) * 32 + c];
    }
    __syncthreads();
    int lane = t & 31;
    int n = blockIdx.x * 8 + (t >> 5);
    if (n >= N) return;
    int beg = rowptr[n], endp = rowptr[n + 1];
    float fD = prec[n * 128 + lane];
    float sD = prec[n * 128 + 64 + lane];
    float acc = 0.f;
    #pragma unroll 2
    for (int idx = beg; idx < endp; idx++) {
        int2 se = adj[idx];                       // warp-broadcast load
        int s = se.x, eid = se.y;
        float f  = fD + __ldg(&prec[s * 128 + 32 + lane]);
        float sv = sD + __ldg(&prec[s * 128 + 96 + lane]);
        float4 ea = *(const float4*)&eattr[eid * EF];
        float4 eb = *(const float4*)&eattr[eid * EF + 4];
        f  = fmaf(ea.x, wfb[0*32+lane], f);  sv = fmaf(ea.x, wsb[0*32+lane], sv);
        f  = fmaf(ea.y, wfb[1*32+lane], f);  sv = fmaf(ea.y, wsb[1*32+lane], sv);
        f  = fmaf(ea.z, wfb[2*32+lane], f);  sv = fmaf(ea.z, wsb[2*32+lane], sv);
        f  = fmaf(ea.w, wfb[3*32+lane], f);  sv = fmaf(ea.w, wsb[3*32+lane], sv);
        f  = fmaf(eb.x, wfb[4*32+lane], f);  sv = fmaf(eb.x, wsb[4*32+lane], sv);
        f  = fmaf(eb.y, wfb[5*32+lane], f);  sv = fmaf(eb.y, wsb[5*32+lane], sv);
        f  = fmaf(eb.z, wfb[6*32+lane], f);  sv = fmaf(eb.z, wsb[6*32+lane], sv);
        f  = fmaf(eb.w, wfb[7*32+lane], f);  sv = fmaf(eb.w, wsb[7*32+lane], sv);
        float sig = 1.f / (1.f + __expf(-f));
        float sp  = fmaxf(sv, 0.f) + __logf(1.f + __expf(-fabsf(sv)));
        acc = fmaf(sig, sp, acc);
    }
    out[n * 32 + lane] = fmaxf(acc + res[n * 32 + lane], 0.f);
}

// ---------------- GAT kernels ----------------
template<int IN, int OUT>
__global__ __launch_bounds__(128) void gat_gemm(
    const float* __restrict__ xin, const float* __restrict__ W,
    float* __restrict__ hg, int N)
{
    __shared__ float wsh[IN * OUT];
    __shared__ float xr[4][IN];
    for (int i = threadIdx.x; i < IN * OUT; i += 128) wsh[i] = W[i];
    __syncthreads();
    int warp = threadIdx.x >> 5, lane = threadIdx.x & 31;
    int n = blockIdx.x * 4 + warp;
    if (n >= N) return;
    for (int k = lane; k < IN; k += 32) xr[warp][k] = xin[n * IN + k];
    __syncwarp();
    #pragma unroll
    for (int j = 0; j < (OUT + 31) / 32; j++) {
        int c = lane + 32 * j;
        if (c < OUT) {
            float a = 0.f;
            #pragma unroll 4
            for (int k = 0; k < IN; k++) a = fmaf(xr[warp][k], wsh[k * OUT + c], a);
            hg[n * OUT + c] = a;
        }
    }
}

template<int C>
__global__ void gat_al(const float* __restrict__ hg,
                       const float* __restrict__ asrc, const float* __restrict__ adst,
                       float* __restrict__ alsrc, float* __restrict__ aldst, int N)
{
    int i = blockIdx.x * blockDim.x + threadIdx.x;
    if (i >= N * HEADS) return;
    int n = i / HEADS, h = i % HEADS;
    float s = 0.f, d = 0.f;
    #pragma unroll 4
    for (int c = 0; c < C; c++) {
        float v = hg[n * HEADS * C + h * C + c];
        s = fmaf(v, asrc[h * C + c], s);
        d = fmaf(v, adst[h * C + c], d);
    }
    alsrc[n * 4 + h] = s; aldst[n * 4 + h] = d;
}

// Fused pull GAT: per dst node, softmax-normalized attention aggregation
// (shift-free: logits O(1), exp safe in fp32; self-loop added explicitly)
template<int OUT, int C>
__global__ __launch_bounds__(256) void gat_pull(
    const float* __restrict__ hg,
    const float* __restrict__ alsrc, const float* __restrict__ aldst,
    const int2* __restrict__ adj, const int* __restrict__ rowptr,
    const float* __restrict__ bias, float* __restrict__ out, int N)
{
    int lane = threadIdx.x & 31;
    int n = blockIdx.x * 8 + (threadIdx.x >> 5);
    if (n >= N) return;
    float4 adv = *(const float4*)&aldst[n * 4];
    float ad0 = adv.x, ad1 = adv.y, ad2 = adv.z;
    constexpr int J = (OUT + 31) / 32;
    float acc[J];
    #pragma unroll
    for (int j = 0; j < J; j++) acc[j] = 0.f;
    float ss0 = 0.f, ss1 = 0.f, ss2 = 0.f;

    int beg = rowptr[n], endp = rowptr[n + 1];
    #pragma unroll 2
    for (int idx = beg - 1; idx < endp; idx++) {
        int s = (idx < beg) ? n : adj[idx].x;   // first iteration = self loop
        float4 asv = *(const float4*)&alsrc[s * 4];   // warp-broadcast
        float e0 = asv.x + ad0, e1 = asv.y + ad1, e2 = asv.z + ad2;
        e0 = (e0 > 0.f) ? e0 : 0.2f * e0;
        e1 = (e1 > 0.f) ? e1 : 0.2f * e1;
        e2 = (e2 > 0.f) ? e2 : 0.2f * e2;
        float p0 = __expf(e0), p1 = __expf(e1), p2 = __expf(e2);
        ss0 += p0; ss1 += p1; ss2 += p2;
        #pragma unroll
        for (int j = 0; j < J; j++) {
            int c = lane + 32 * j;
            if (c < OUT) {
                int h = c / C;
                float pv = (h == 0) ? p0 : ((h == 1) ? p1 : p2);
                acc[j] = fmaf(__ldg(&hg[s * OUT + c]), pv, acc[j]);
            }
        }
    }
    #pragma unroll
    for (int j = 0; j < J; j++) {
        int c = lane + 32 * j;
        if (c < OUT) {
            int h = c / C;
            float ss = (h == 0) ? ss0 : ((h == 1) ? ss1 : ss2);
            out[n * OUT + c] = fmaxf(acc[j] / (ss + 1e-16f) + bias[c], 0.f);
        }
    }
}

// ---------------- pooling + head ----------------
__global__ void pool_kernel(const float* __restrict__ g2, const int* __restrict__ batch,
                            float* __restrict__ pooled, float* __restrict__ cnt, int N)
{
    int i = blockIdx.x * blockDim.x + threadIdx.x;
    if (i >= N * G2O) return;
    int n = i / G2O, c = i % G2O;
    int b = batch[n];
    atomicAdd(&pooled[b * G2O + c], g2[i]);
    if (c == 0) atomicAdd(&cnt[b], 1.f);
}

__global__ void head_kernel(const float* __restrict__ pooled, const float* __restrict__ cnt,
                            const float* __restrict__ Wl1, const float* __restrict__ bl1,
                            const float* __restrict__ Wl2, const float* __restrict__ bl2,
                            float* __restrict__ out)
{
    __shared__ float mean[G2O];
    __shared__ float l1[16];
    int g = blockIdx.x, t = threadIdx.x;
    float c = fmaxf(cnt[g], 1.f);
    if (t < G2O) mean[t] = pooled[g * G2O + t] / c;
    __syncthreads();
    if (t < 16) {
        float a = bl1[t];
        #pragma unroll 4
        for (int k = 0; k < G2O; k++) a = fmaf(mean[k], Wl1[k * 16 + t], a);
        l1[t] = fmaxf(a, 0.f);
    }
    __syncthreads();
    if (t < 10) {
        float a = bl2[t];
        #pragma unroll
        for (int k = 0; k < 16; k++) a = fmaf(l1[k], Wl2[k * 10 + t], a);
        out[g * 10 + t] = a;
    }
}

// ---------------- launch ----------------
static inline int cdiv(int a, int b) { return (a + b - 1) / b; }

extern "C" void kernel_launch(void* const* d_in, const int* in_sizes, int n_in,
                              void* d_out, int out_size)
{
    const float* x     = (const float*)d_in[0];
    const float* eattr = (const float*)d_in[1];
    const int*   eidx  = (const int*)  d_in[2];
    const int*   batch = (const int*)  d_in[3];
    const float* Wf1 = (const float*)d_in[4];  const float* bf1 = (const float*)d_in[5];
    const float* Ws1 = (const float*)d_in[6];  const float* bs1 = (const float*)d_in[7];
    const float* Wf2 = (const float*)d_in[8];  const float* bf2 = (const float*)d_in[9];
    const float* Ws2 = (const float*)d_in[10]; const float* bs2 = (const float*)d_in[11];
    const float* Wg1 = (const float*)d_in[12];
    const float* as1 = (const float*)d_in[13]; const float* ad1 = (const float*)d_in[14];
    const float* bg1 = (const float*)d_in[15];
    const float* Wg2 = (const float*)d_in[16];
    const float* as2 = (const float*)d_in[17]; const float* ad2 = (const float*)d_in[18];
    const float* bg2 = (const float*)d_in[19];
    const float* Wl1 = (const float*)d_in[20]; const float* bl1 = (const float*)d_in[21];
    const float* Wl2 = (const float*)d_in[22]; const float* bl2 = (const float*)d_in[23];
    float* out = (float*)d_out;

    const int N = in_sizes[0] / NF;
    const int E = in_sizes[2] / 2;
    const int* src = eidx;
    const int* dst = eidx + E;

    float *h1, *h2, *prec, *bufA, *bufC, *alsrc, *aldst, *pool, *cnt;
    int *deg, *rowptr, *cursor; int2* adj;
    cudaGetSymbolAddress((void**)&h1,   d_h1);
    cudaGetSymbolAddress((void**)&h2,   d_h2);
    cudaGetSymbolAddress((void**)&prec, d_prec);
    cudaGetSymbolAddress((void**)&bufA, d_bufA);
    cudaGetSymbolAddress((void**)&bufC, d_bufC);
    cudaGetSymbolAddress((void**)&alsrc,d_alsrc);
    cudaGetSymbolAddress((void**)&aldst,d_aldst);
    cudaGetSymbolAddress((void**)&pool, d_pool);
    cudaGetSymbolAddress((void**)&cnt,  d_cnt);
    cudaGetSymbolAddress((void**)&deg,    d_deg);
    cudaGetSymbolAddress((void**)&rowptr, d_rowptr);
    cudaGetSymbolAddress((void**)&cursor, d_cursor);
    cudaGetSymbolAddress((void**)&adj,    d_adj);

    const int NODEB = cdiv(N, 8);     // warp-per-node kernels

    // ---- CSR build (reused by all 4 edge passes) ----
    fill_i<<<cdiv(N,256),256>>>(deg, 0, N);
    csr_hist<<<cdiv(E,256),256>>>(dst, deg, E);
    csr_scan<<<1,1024>>>(deg, rowptr, cursor, N);
    csr_scatter<<<cdiv(E,256),256>>>(src, dst, cursor, adj, E);

    // ---- CGConv 1 ----
    cg_node_pre<<<cdiv(N,8),256>>>(x, Wf1, bf1, Ws1, bs1, prec, N);
    cg_pull<<<NODEB,256>>>(prec, eattr, adj, rowptr, Wf1, Ws1, x, h1, N);

    // ---- CGConv 2 ----
    cg_node_pre<<<cdiv(N,8),256>>>(h1, Wf2, bf2, Ws2, bs2, prec, N);
    cg_pull<<<NODEB,256>>>(prec, eattr, adj, rowptr, Wf2, Ws2, h1, h2, N);

    // ---- GAT 1 (32 -> 3x32) ----
    gat_gemm<NF, G1O><<<cdiv(N,4),128>>>(h2, Wg1, bufA, N);
    gat_al<G1C><<<cdiv(N*HEADS,256),256>>>(bufA, as1, ad1, alsrc, aldst, N);
    gat_pull<G1O, G1C><<<NODEB,256>>>(bufA, alsrc, aldst, adj, rowptr, bg1, bufC, N);

    // ---- GAT 2 (96 -> 3x16) ----
    gat_gemm<G1O, G2O><<<cdiv(N,4),128>>>(bufC, Wg2, bufA, N);
    gat_al<G2C><<<cdiv(N*HEADS,256),256>>>(bufA, as2, ad2, alsrc, aldst, N);
    gat_pull<G2O, G2C><<<NODEB,256>>>(bufA, alsrc, aldst, adj, rowptr, bg2, bufC, N);

    // ---- pool + head ----
    fill_f<<<cdiv(NG*G2O,256),256>>>(pool, 0.f, NG*G2O);
    fill_f<<<1,64>>>(cnt, 0.f, NG);
    pool_kernel<<<cdiv(N*G2O,256),256>>>(bufC, batch, pool, cnt, N);
    head_kernel<<<NG,64>>>(pool, cnt, Wl1, bl1, Wl2, bl2, out);
}

// round 7
// speedup vs baseline: 2.1053x; 1.0348x over previous
#include <cuda_runtime.h>
#include <cuda_bf16.h>
#include <math.h>

// ---------------- problem constants ----------------
#define NN 50000
#define NE 800000
#define NF 32
#define EF 8
#define HEADS 3
#define NG 64
#define G1C 32
#define G2C 16
#define G1O (HEADS*G1C)   // 96
#define G2O (HEADS*G2C)   // 48

// ---------------- device scratch (16B-aligned: vector loads used) ----------------
__device__ __align__(16) float d_h1  [NN*NF];
__device__ __align__(16) float d_h2  [NN*NF];
__device__ __align__(16) float d_prec[NN*128];   // [fD|fS|sD|sS] x32
__device__ __align__(16) float d_bufA[NN*G1O];   // hg
__device__ __align__(16) float d_bufC[NN*G1O];   // layer outputs
__device__ __align__(16) float d_alsrc[NN*4];    // padded to 4 for float4 loads
__device__ __align__(16) float d_aldst[NN*4];
__device__ __align__(16) float d_pool[NG*G2O];
__device__ float d_cnt [NG];
// CSR
__device__ int  d_deg   [NN];
__device__ int  d_rowptr[NN + 1];
__device__ int  d_cursor[NN];
__device__ __align__(16) int2 d_adj[NE];         // (src, edge_id) sorted by dst

// ---------------- utility ----------------
__global__ void fill_f(float* p, float v, int n) {
    int i = blockIdx.x * blockDim.x + threadIdx.x;
    if (i < n) p[i] = v;
}
__global__ void fill_i(int* p, int v, int n) {
    int i = blockIdx.x * blockDim.x + threadIdx.x;
    if (i < n) p[i] = v;
}

// ---------------- CSR construction ----------------
__global__ void csr_hist(const int* __restrict__ dst, int* __restrict__ deg, int E) {
    int i = blockIdx.x * blockDim.x + threadIdx.x;
    if (i < E) atomicAdd(&deg[dst[i]], 1);
}

__global__ __launch_bounds__(1024) void csr_scan(const int* __restrict__ deg,
                                                 int* __restrict__ rowptr,
                                                 int* __restrict__ cursor, int N)
{
    __shared__ int tsum[1024];
    int t = threadIdx.x;
    int per = (N + 1023) / 1024;
    int start = t * per, end = min(start + per, N);
    int s = 0;
    for (int i = start; i < end; i++) s += deg[i];
    tsum[t] = s;
    __syncthreads();
    int inc = s;
    for (int off = 1; off < 1024; off <<= 1) {
        int v = (t >= off) ? tsum[t - off] : 0;
        __syncthreads();
        tsum[t] += v;
        __syncthreads();
    }
    int run = tsum[t] - inc;
    for (int i = start; i < end; i++) {
        rowptr[i] = run; cursor[i] = run;
        run += deg[i];
    }
    if (t == 1023) rowptr[N] = run;
}

__global__ void csr_scatter(const int* __restrict__ src, const int* __restrict__ dst,
                            int* __restrict__ cursor, int2* __restrict__ adj, int E)
{
    int i = blockIdx.x * blockDim.x + threadIdx.x;
    if (i < E) {
        int d = dst[i];
        int pos = atomicAdd(&cursor[d], 1);
        adj[pos] = make_int2(src[i], i);
    }
}

// ---------------- CGConv: node precompute (grid-strided; weights loaded once) ----
__global__ __launch_bounds__(256) void cg_node_pre(
    const float* __restrict__ x,
    const float* __restrict__ Wf, const float* __restrict__ bf,
    const float* __restrict__ Ws, const float* __restrict__ bs,
    float* __restrict__ prec, int N)
{
    __shared__ float wc[32 * 128];
    for (int idx = threadIdx.x; idx < 32 * 128; idx += 256) {
        int k = idx >> 7, c = idx & 127;
        float v;
        if      (c < 32)  v = Wf[k * 32 + c];
        else if (c < 64)  v = Wf[(32 + k) * 32 + (c - 32)];
        else if (c < 96)  v = Ws[k * 32 + (c - 64)];
        else              v = Ws[(32 + k) * 32 + (c - 96)];
        wc[idx] = v;
    }
    __syncthreads();
    int warp = threadIdx.x >> 5, lane = threadIdx.x & 31;
    int cbase = lane * 4;
    for (int n = blockIdx.x * 8 + warp; n < N; n += gridDim.x * 8) {
        float xv = x[n * 32 + lane];
        float4 acc = make_float4(0.f, 0.f, 0.f, 0.f);
        #pragma unroll
        for (int k = 0; k < 32; k++) {
            float xk = __shfl_sync(0xffffffffu, xv, k);
            float4 w = *(const float4*)&wc[k * 128 + cbase];
            acc.x = fmaf(xk, w.x, acc.x);
            acc.y = fmaf(xk, w.y, acc.y);
            acc.z = fmaf(xk, w.z, acc.z);
            acc.w = fmaf(xk, w.w, acc.w);
        }
        if (cbase < 32) {
            acc.x += bf[cbase]; acc.y += bf[cbase+1]; acc.z += bf[cbase+2]; acc.w += bf[cbase+3];
        } else if (cbase >= 64 && cbase < 96) {
            int b0 = cbase - 64;
            acc.x += bs[b0]; acc.y += bs[b0+1]; acc.z += bs[b0+2]; acc.w += bs[b0+3];
        }
        *(float4*)&prec[n * 128 + cbase] = acc;
    }
}

// ---------------- CGConv: pull aggregation (warp per dst node) ----------------
__global__ __launch_bounds__(256) void cg_pull(
    const float* __restrict__ prec, const float* __restrict__ eattr,
    const int2* __restrict__ adj, const int* __restrict__ rowptr,
    const float* __restrict__ Wf, const float* __restrict__ Ws,
    const float* __restrict__ res, float* __restrict__ out, int N)
{
    __shared__ float wfb[EF * 32], wsb[EF * 32];
    int t = threadIdx.x;
    if (t < EF * 32) {
        int k = t >> 5, c = t & 31;
        wfb[t] = Wf[(64 + k) * 32 + c];
        wsb[t] = Ws[(64 + k) * 32 + c];
    }
    __syncthreads();
    int lane = t & 31;
    int n = blockIdx.x * 8 + (t >> 5);
    if (n >= N) return;
    int beg = rowptr[n], endp = rowptr[n + 1];
    float fD = prec[n * 128 + lane];
    float sD = prec[n * 128 + 64 + lane];
    float acc = 0.f;
    #pragma unroll 4
    for (int idx = beg; idx < endp; idx++) {
        int2 se = adj[idx];
        int s = se.x, eid = se.y;
        float f  = fD + __ldg(&prec[s * 128 + 32 + lane]);
        float sv = sD + __ldg(&prec[s * 128 + 96 + lane]);
        float4 ea = *(const float4*)&eattr[eid * EF];
        float4 eb = *(const float4*)&eattr[eid * EF + 4];
        f  = fmaf(ea.x, wfb[0*32+lane], f);  sv = fmaf(ea.x, wsb[0*32+lane], sv);
        f  = fmaf(ea.y, wfb[1*32+lane], f);  sv = fmaf(ea.y, wsb[1*32+lane], sv);
        f  = fmaf(ea.z, wfb[2*32+lane], f);  sv = fmaf(ea.z, wsb[2*32+lane], sv);
        f  = fmaf(ea.w, wfb[3*32+lane], f);  sv = fmaf(ea.w, wsb[3*32+lane], sv);
        f  = fmaf(eb.x, wfb[4*32+lane], f);  sv = fmaf(eb.x, wsb[4*32+lane], sv);
        f  = fmaf(eb.y, wfb[5*32+lane], f);  sv = fmaf(eb.y, wsb[5*32+lane], sv);
        f  = fmaf(eb.z, wfb[6*32+lane], f);  sv = fmaf(eb.z, wsb[6*32+lane], sv);
        f  = fmaf(eb.w, wfb[7*32+lane], f);  sv = fmaf(eb.w, wsb[7*32+lane], sv);
        float sig = 1.f / (1.f + __expf(-f));
        float sp  = fmaxf(sv, 0.f) + __logf(1.f + __expf(-fabsf(sv)));
        acc = fmaf(sig, sp, acc);
    }
    out[n * 32 + lane] = fmaxf(acc + res[n * 32 + lane], 0.f);
}

// ---------------- GAT kernels ----------------
// node transform, grid-strided: weights loaded to SMEM once per block
template<int IN, int OUT>
__global__ __launch_bounds__(256) void gat_gemm(
    const float* __restrict__ xin, const float* __restrict__ W,
    float* __restrict__ hg, int N)
{
    __shared__ float wsh[IN * OUT];
    __shared__ float xr[8][IN];
    for (int i = threadIdx.x; i < IN * OUT; i += 256) wsh[i] = W[i];
    __syncthreads();
    int warp = threadIdx.x >> 5, lane = threadIdx.x & 31;
    for (int n = blockIdx.x * 8 + warp; n < N; n += gridDim.x * 8) {
        #pragma unroll
        for (int k = lane; k < IN; k += 32) xr[warp][k] = xin[n * IN + k];
        __syncwarp();
        #pragma unroll
        for (int j = 0; j < (OUT + 31) / 32; j++) {
            int c = lane + 32 * j;
            if (c < OUT) {
                float a = 0.f;
                #pragma unroll 8
                for (int k = 0; k < IN; k++) a = fmaf(xr[warp][k], wsh[k * OUT + c], a);
                hg[n * OUT + c] = a;
            }
        }
        __syncwarp();
    }
}

template<int C>
__global__ void gat_al(const float* __restrict__ hg,
                       const float* __restrict__ asrc, const float* __restrict__ adst,
                       float* __restrict__ alsrc, float* __restrict__ aldst, int N)
{
    int i = blockIdx.x * blockDim.x + threadIdx.x;
    if (i >= N * HEADS) return;
    int n = i / HEADS, h = i % HEADS;
    float s = 0.f, d = 0.f;
    #pragma unroll 4
    for (int c = 0; c < C; c++) {
        float v = hg[n * HEADS * C + h * C + c];
        s = fmaf(v, asrc[h * C + c], s);
        d = fmaf(v, adst[h * C + c], d);
    }
    alsrc[n * 4 + h] = s; aldst[n * 4 + h] = d;
}

// Fused pull GAT (shift-free softmax; explicit self-loop first iteration)
template<int OUT, int C>
__global__ __launch_bounds__(256) void gat_pull(
    const float* __restrict__ hg,
    const float* __restrict__ alsrc, const float* __restrict__ aldst,
    const int2* __restrict__ adj, const int* __restrict__ rowptr,
    const float* __restrict__ bias, float* __restrict__ out, int N)
{
    int lane = threadIdx.x & 31;
    int n = blockIdx.x * 8 + (threadIdx.x >> 5);
    if (n >= N) return;
    float4 adv = *(const float4*)&aldst[n * 4];
    float ad0 = adv.x, ad1 = adv.y, ad2 = adv.z;
    constexpr int J = (OUT + 31) / 32;
    float acc[J];
    #pragma unroll
    for (int j = 0; j < J; j++) acc[j] = 0.f;
    float ss0 = 0.f, ss1 = 0.f, ss2 = 0.f;

    int beg = rowptr[n], endp = rowptr[n + 1];
    #pragma unroll 4
    for (int idx = beg - 1; idx < endp; idx++) {
        int s = (idx < beg) ? n : adj[idx].x;
        float4 asv = *(const float4*)&alsrc[s * 4];
        float e0 = asv.x + ad0, e1 = asv.y + ad1, e2 = asv.z + ad2;
        e0 = (e0 > 0.f) ? e0 : 0.2f * e0;
        e1 = (e1 > 0.f) ? e1 : 0.2f * e1;
        e2 = (e2 > 0.f) ? e2 : 0.2f * e2;
        float p0 = __expf(e0), p1 = __expf(e1), p2 = __expf(e2);
        ss0 += p0; ss1 += p1; ss2 += p2;
        #pragma unroll
        for (int j = 0; j < J; j++) {
            int c = lane + 32 * j;
            if (c < OUT) {
                int h = c / C;
                float pv = (h == 0) ? p0 : ((h == 1) ? p1 : p2);
                acc[j] = fmaf(__ldg(&hg[s * OUT + c]), pv, acc[j]);
            }
        }
    }
    #pragma unroll
    for (int j = 0; j < J; j++) {
        int c = lane + 32 * j;
        if (c < OUT) {
            int h = c / C;
            float ss = (h == 0) ? ss0 : ((h == 1) ? ss1 : ss2);
            out[n * OUT + c] = fmaxf(acc[j] / (ss + 1e-16f) + bias[c], 0.f);
        }
    }
}

// ---------------- pooling + head ----------------
__global__ void pool_kernel(const float* __restrict__ g2, const int* __restrict__ batch,
                            float* __restrict__ pooled, float* __restrict__ cnt, int N)
{
    int i = blockIdx.x * blockDim.x + threadIdx.x;
    if (i >= N * G2O) return;
    int n = i / G2O, c = i % G2O;
    int b = batch[n];
    atomicAdd(&pooled[b * G2O + c], g2[i]);
    if (c == 0) atomicAdd(&cnt[b], 1.f);
}

__global__ void head_kernel(const float* __restrict__ pooled, const float* __restrict__ cnt,
                            const float* __restrict__ Wl1, const float* __restrict__ bl1,
                            const float* __restrict__ Wl2, const float* __restrict__ bl2,
                            float* __restrict__ out)
{
    __shared__ float mean[G2O];
    __shared__ float l1[16];
    int g = blockIdx.x, t = threadIdx.x;
    float c = fmaxf(cnt[g], 1.f);
    if (t < G2O) mean[t] = pooled[g * G2O + t] / c;
    __syncthreads();
    if (t < 16) {
        float a = bl1[t];
        #pragma unroll 4
        for (int k = 0; k < G2O; k++) a = fmaf(mean[k], Wl1[k * 16 + t], a);
        l1[t] = fmaxf(a, 0.f);
    }
    __syncthreads();
    if (t < 10) {
        float a = bl2[t];
        #pragma unroll
        for (int k = 0; k < 16; k++) a = fmaf(l1[k], Wl2[k * 10 + t], a);
        out[g * 10 + t] = a;
    }
}

// ---------------- launch ----------------
static inline int cdiv(int a, int b) { return (a + b - 1) / b; }

extern "C" void kernel_launch(void* const* d_in, const int* in_sizes, int n_in,
                              void* d_out, int out_size)
{
    const float* x     = (const float*)d_in[0];
    const float* eattr = (const float*)d_in[1];
    const int*   eidx  = (const int*)  d_in[2];
    const int*   batch = (const int*)  d_in[3];
    const float* Wf1 = (const float*)d_in[4];  const float* bf1 = (const float*)d_in[5];
    const float* Ws1 = (const float*)d_in[6];  const float* bs1 = (const float*)d_in[7];
    const float* Wf2 = (const float*)d_in[8];  const float* bf2 = (const float*)d_in[9];
    const float* Ws2 = (const float*)d_in[10]; const float* bs2 = (const float*)d_in[11];
    const float* Wg1 = (const float*)d_in[12];
    const float* as1 = (const float*)d_in[13]; const float* ad1 = (const float*)d_in[14];
    const float* bg1 = (const float*)d_in[15];
    const float* Wg2 = (const float*)d_in[16];
    const float* as2 = (const float*)d_in[17]; const float* ad2 = (const float*)d_in[18];
    const float* bg2 = (const float*)d_in[19];
    const float* Wl1 = (const float*)d_in[20]; const float* bl1 = (const float*)d_in[21];
    const float* Wl2 = (const float*)d_in[22]; const float* bl2 = (const float*)d_in[23];
    float* out = (float*)d_out;

    const int N = in_sizes[0] / NF;
    const int E = in_sizes[2] / 2;
    const int* src = eidx;
    const int* dst = eidx + E;

    float *h1, *h2, *prec, *bufA, *bufC, *alsrc, *aldst, *pool, *cnt;
    int *deg, *rowptr, *cursor; int2* adj;
    cudaGetSymbolAddress((void**)&h1,   d_h1);
    cudaGetSymbolAddress((void**)&h2,   d_h2);
    cudaGetSymbolAddress((void**)&prec, d_prec);
    cudaGetSymbolAddress((void**)&bufA, d_bufA);
    cudaGetSymbolAddress((void**)&bufC, d_bufC);
    cudaGetSymbolAddress((void**)&alsrc,d_alsrc);
    cudaGetSymbolAddress((void**)&aldst,d_aldst);
    cudaGetSymbolAddress((void**)&pool, d_pool);
    cudaGetSymbolAddress((void**)&cnt,  d_cnt);
    cudaGetSymbolAddress((void**)&deg,    d_deg);
    cudaGetSymbolAddress((void**)&rowptr, d_rowptr);
    cudaGetSymbolAddress((void**)&cursor, d_cursor);
    cudaGetSymbolAddress((void**)&adj,    d_adj);

    const int NODEB = cdiv(N, 8);      // warp-per-node pull kernels
    const int GSGRID = 592;            // grid-strided node GEMMs: 4 blocks/SM

    // ---- CSR build (reused by all 4 edge passes) ----
    fill_i<<<cdiv(N,256),256>>>(deg, 0, N);
    csr_hist<<<cdiv(E,256),256>>>(dst, deg, E);
    csr_scan<<<1,1024>>>(deg, rowptr, cursor, N);
    csr_scatter<<<cdiv(E,256),256>>>(src, dst, cursor, adj, E);

    // ---- CGConv 1 ----
    cg_node_pre<<<GSGRID,256>>>(x, Wf1, bf1, Ws1, bs1, prec, N);
    cg_pull<<<NODEB,256>>>(prec, eattr, adj, rowptr, Wf1, Ws1, x, h1, N);

    // ---- CGConv 2 ----
    cg_node_pre<<<GSGRID,256>>>(h1, Wf2, bf2, Ws2, bs2, prec, N);
    cg_pull<<<NODEB,256>>>(prec, eattr, adj, rowptr, Wf2, Ws2, h1, h2, N);

    // ---- GAT 1 (32 -> 3x32) ----
    gat_gemm<NF, G1O><<<GSGRID,256>>>(h2, Wg1, bufA, N);
    gat_al<G1C><<<cdiv(N*HEADS,256),256>>>(bufA, as1, ad1, alsrc, aldst, N);
    gat_pull<G1O, G1C><<<NODEB,256>>>(bufA, alsrc, aldst, adj, rowptr, bg1, bufC, N);

    // ---- GAT 2 (96 -> 3x16) ----
    gat_gemm<G1O, G2O><<<GSGRID,256>>>(bufC, Wg2, bufA, N);
    gat_al<G2C><<<cdiv(N*HEADS,256),256>>>(bufA, as2, ad2, alsrc, aldst, N);
    gat_pull<G2O, G2C><<<NODEB,256>>>(bufA, alsrc, aldst, adj, rowptr, bg2, bufC, N);

    // ---- pool + head ----
    fill_f<<<cdiv(NG*G2O,256),256>>>(pool, 0.f, NG*G2O);
    fill_f<<<1,64>>>(cnt, 0.f, NG);
    pool_kernel<<<cdiv(N*G2O,256),256>>>(bufC, batch, pool, cnt, N);
    head_kernel<<<NG,64>>>(pool, cnt, Wl1, bl1, Wl2, bl2, out);
}